// round 7
// baseline (speedup 1.0000x reference)
#include <cuda_runtime.h>
#include <cuda_bf16.h>
#include <cuda_fp16.h>
#include <stdint.h>

#define N_NODES 50000
#define N_EDGES 800000
#define F_IN 128
#define HID 256

// Scratch (allocation-free rule: __device__ globals)
__device__ __align__(16) float g_agg[(size_t)N_NODES * HID];
__device__ __align__(16) float g_h1[(size_t)N_NODES * HID];
__device__ __align__(16) __half g_x16[(size_t)N_NODES * F_IN];
__device__ __align__(16) __half g_h116[(size_t)N_NODES * HID];
__device__ int g_deg[N_NODES];
__device__ int g_off[N_NODES + 1];
__device__ int g_cur[N_NODES];
__device__ int g_srcs[N_EDGES];

// bf16 hi/lo split weights
__device__ __align__(16) __nv_bfloat16 g_w1l_h[256 * 128];
__device__ __align__(16) __nv_bfloat16 g_w1l_l[256 * 128];
__device__ __align__(16) __nv_bfloat16 g_w1r_h[256 * 128];
__device__ __align__(16) __nv_bfloat16 g_w1r_l[256 * 128];
__device__ __align__(16) __nv_bfloat16 g_w2l_h[256 * 256];
__device__ __align__(16) __nv_bfloat16 g_w2l_l[256 * 256];
__device__ __align__(16) __nv_bfloat16 g_w2r_h[256 * 256];
__device__ __align__(16) __nv_bfloat16 g_w2r_l[256 * 256];

// ---------------------------------------------------------------------------
__global__ void k_zero_int(int* __restrict__ p, int n) {
    int i = blockIdx.x * blockDim.x + threadIdx.x;
    if (i < n) p[i] = 0;
}

__global__ void k_hist(const int* __restrict__ ei) {
    int e = blockIdx.x * blockDim.x + threadIdx.x;
    if (e >= N_EDGES) return;
    atomicAdd(&g_deg[ei[N_EDGES + e]], 1);
}

__global__ __launch_bounds__(1024) void k_scan() {
    __shared__ int ssum[1024];
    const int CH = (N_NODES + 1023) / 1024;
    int tid = threadIdx.x;
    int base = tid * CH;
    int s = 0;
    for (int i = 0; i < CH; ++i) {
        int idx = base + i;
        if (idx < N_NODES) s += g_deg[idx];
    }
    ssum[tid] = s;
    __syncthreads();
    for (int d = 1; d < 1024; d <<= 1) {
        int v = (tid >= d) ? ssum[tid - d] : 0;
        __syncthreads();
        ssum[tid] += v;
        __syncthreads();
    }
    int run = (tid == 0) ? 0 : ssum[tid - 1];
    for (int i = 0; i < CH; ++i) {
        int idx = base + i;
        if (idx < N_NODES) {
            g_off[idx] = run;
            g_cur[idx] = run;
            run += g_deg[idx];
        }
    }
    if (tid == 1023) g_off[N_NODES] = N_EDGES;
}

__global__ void k_fill(const int* __restrict__ ei) {
    int e = blockIdx.x * blockDim.x + threadIdx.x;
    if (e >= N_EDGES) return;
    int src = ei[e];
    int dst = ei[N_EDGES + e];
    int pos = atomicAdd(&g_cur[dst], 1);
    g_srcs[pos] = src;
}

// ---------------------------------------------------------------------------
// fp32 -> fp16 convert (vectorized x4)
__global__ void k_f2h(const float* __restrict__ src, __half* __restrict__ dst, int n4) {
    int i = blockIdx.x * blockDim.x + threadIdx.x;
    if (i >= n4) return;
    float4 v = ((const float4*)src)[i];
    __half2 h0 = __floats2half2_rn(v.x, v.y);
    __half2 h1 = __floats2half2_rn(v.z, v.w);
    uint2 u;
    u.x = *(uint32_t*)&h0;
    u.y = *(uint32_t*)&h1;
    ((uint2*)dst)[i] = u;
}

// all 4 weight splits in one launch (grid.y selects array)
__global__ void k_wconv_all(const float* __restrict__ s0, const float* __restrict__ s1,
                            const float* __restrict__ s2, const float* __restrict__ s3,
                            __nv_bfloat16* __restrict__ h0, __nv_bfloat16* __restrict__ l0,
                            __nv_bfloat16* __restrict__ h1p, __nv_bfloat16* __restrict__ l1,
                            __nv_bfloat16* __restrict__ h2, __nv_bfloat16* __restrict__ l2,
                            __nv_bfloat16* __restrict__ h3, __nv_bfloat16* __restrict__ l3) {
    int y = blockIdx.y;
    int n = (y < 2) ? 256 * 128 : 256 * 256;
    int i = blockIdx.x * blockDim.x + threadIdx.x;
    if (i >= n) return;
    const float* s = (y == 0) ? s0 : (y == 1) ? s1 : (y == 2) ? s2 : s3;
    __nv_bfloat16* hh = (y == 0) ? h0 : (y == 1) ? h1p : (y == 2) ? h2 : h3;
    __nv_bfloat16* ll = (y == 0) ? l0 : (y == 1) ? l1 : (y == 2) ? l2 : l3;
    float v = s[i];
    __nv_bfloat16 h = __float2bfloat16(v);
    hh[i] = h;
    ll[i] = __float2bfloat16(v - __bfloat162float(h));
}

// ---------------------------------------------------------------------------
// gather-mean, F=128 from fp16: warp per node, lane holds 4 halves (8B)
__global__ void k_agg1(const __half* __restrict__ x16) {
    int node = (blockIdx.x * blockDim.x + threadIdx.x) >> 5;
    int lane = threadIdx.x & 31;
    if (node >= N_NODES) return;
    int beg = g_off[node], end = g_off[node + 1];
    float2 a0 = make_float2(0.f, 0.f), a1 = make_float2(0.f, 0.f);
    int e = beg;
    for (; e + 4 <= end; e += 4) {
        int s0 = g_srcs[e], s1 = g_srcs[e + 1], s2 = g_srcs[e + 2], s3 = g_srcs[e + 3];
        uint2 v0 = ((const uint2*)(x16 + (size_t)s0 * F_IN))[lane];
        uint2 v1 = ((const uint2*)(x16 + (size_t)s1 * F_IN))[lane];
        uint2 v2 = ((const uint2*)(x16 + (size_t)s2 * F_IN))[lane];
        uint2 v3 = ((const uint2*)(x16 + (size_t)s3 * F_IN))[lane];
#pragma unroll
        for (int q = 0; q < 4; ++q) {
            uint2 v = (q == 0) ? v0 : (q == 1) ? v1 : (q == 2) ? v2 : v3;
            float2 f0 = __half22float2(*(__half2*)&v.x);
            float2 f1 = __half22float2(*(__half2*)&v.y);
            a0.x += f0.x; a0.y += f0.y; a1.x += f1.x; a1.y += f1.y;
        }
    }
    for (; e < end; ++e) {
        int s = g_srcs[e];
        uint2 v = ((const uint2*)(x16 + (size_t)s * F_IN))[lane];
        float2 f0 = __half22float2(*(__half2*)&v.x);
        float2 f1 = __half22float2(*(__half2*)&v.y);
        a0.x += f0.x; a0.y += f0.y; a1.x += f1.x; a1.y += f1.y;
    }
    float inv = (end > beg) ? 1.0f / (float)(end - beg) : 0.0f;
    float4 r = make_float4(a0.x * inv, a0.y * inv, a1.x * inv, a1.y * inv);
    *(float4*)(g_agg + (size_t)node * F_IN + lane * 4) = r;
}

// gather-mean, F=256 from fp16: warp per node, lane holds 8 halves (16B)
__global__ void k_agg2(const __half* __restrict__ h16) {
    int node = (blockIdx.x * blockDim.x + threadIdx.x) >> 5;
    int lane = threadIdx.x & 31;
    if (node >= N_NODES) return;
    int beg = g_off[node], end = g_off[node + 1];
    float a[8];
#pragma unroll
    for (int q = 0; q < 8; ++q) a[q] = 0.f;
    int e = beg;
    for (; e + 4 <= end; e += 4) {
        int s0 = g_srcs[e], s1 = g_srcs[e + 1], s2 = g_srcs[e + 2], s3 = g_srcs[e + 3];
        uint4 v0 = ((const uint4*)(h16 + (size_t)s0 * HID))[lane];
        uint4 v1 = ((const uint4*)(h16 + (size_t)s1 * HID))[lane];
        uint4 v2 = ((const uint4*)(h16 + (size_t)s2 * HID))[lane];
        uint4 v3 = ((const uint4*)(h16 + (size_t)s3 * HID))[lane];
#pragma unroll
        for (int q = 0; q < 4; ++q) {
            uint4 v = (q == 0) ? v0 : (q == 1) ? v1 : (q == 2) ? v2 : v3;
            float2 f0 = __half22float2(*(__half2*)&v.x);
            float2 f1 = __half22float2(*(__half2*)&v.y);
            float2 f2 = __half22float2(*(__half2*)&v.z);
            float2 f3 = __half22float2(*(__half2*)&v.w);
            a[0] += f0.x; a[1] += f0.y; a[2] += f1.x; a[3] += f1.y;
            a[4] += f2.x; a[5] += f2.y; a[6] += f3.x; a[7] += f3.y;
        }
    }
    for (; e < end; ++e) {
        int s = g_srcs[e];
        uint4 v = ((const uint4*)(h16 + (size_t)s * HID))[lane];
        float2 f0 = __half22float2(*(__half2*)&v.x);
        float2 f1 = __half22float2(*(__half2*)&v.y);
        float2 f2 = __half22float2(*(__half2*)&v.z);
        float2 f3 = __half22float2(*(__half2*)&v.w);
        a[0] += f0.x; a[1] += f0.y; a[2] += f1.x; a[3] += f1.y;
        a[4] += f2.x; a[5] += f2.y; a[6] += f3.x; a[7] += f3.y;
    }
    float inv = (end > beg) ? 1.0f / (float)(end - beg) : 0.0f;
    float* dst = g_agg + (size_t)node * HID + lane * 8;
    *(float4*)dst = make_float4(a[0] * inv, a[1] * inv, a[2] * inv, a[3] * inv);
    *(float4*)(dst + 4) = make_float4(a[4] * inv, a[5] * inv, a[6] * inv, a[7] * inv);
}

// ---------------------------------------------------------------------------
// Tensor-core fused double-GEMM (bf16x3 split, fp32 accum):
//   C[n,256] = act(A1 @ W1^T + A2 @ W2^T + bias), optional fp16 copy of C
#define MMA_BF16(d, a, b)                                                     \
    asm volatile(                                                             \
        "mma.sync.aligned.m16n8k16.row.col.f32.bf16.bf16.f32 "                \
        "{%0,%1,%2,%3}, {%4,%5,%6,%7}, {%8,%9}, {%0,%1,%2,%3};"               \
        : "+f"((d)[0]), "+f"((d)[1]), "+f"((d)[2]), "+f"((d)[3])              \
        : "r"((a)[0]), "r"((a)[1]), "r"((a)[2]), "r"((a)[3]),                 \
          "r"((b)[0]), "r"((b)[1]))

template <int K, bool RELU, bool H16>
__global__ __launch_bounds__(256) void k_gemm_tc(
    const float* __restrict__ A1, const __nv_bfloat16* __restrict__ W1h,
    const __nv_bfloat16* __restrict__ W1lo,
    const float* __restrict__ A2, const __nv_bfloat16* __restrict__ W2h,
    const __nv_bfloat16* __restrict__ W2lo,
    const float* __restrict__ bias, float* __restrict__ C,
    __half* __restrict__ C16, int nrows) {
    constexpr int LD = 40;
    __shared__ __nv_bfloat16 sAh[128 * LD];
    __shared__ __nv_bfloat16 sAl[128 * LD];
    __shared__ __nv_bfloat16 sBh[128 * LD];
    __shared__ __nv_bfloat16 sBl[128 * LD];

    int tid = threadIdx.x;
    int wid = tid >> 5, lane = tid & 31;
    int g = lane >> 2, t = lane & 3;
    int warp_m = wid & 3;
    int warp_n = wid >> 2;
    int row0 = blockIdx.x * 128, col0 = blockIdx.y * 128;

    float acc[2][8][4];
#pragma unroll
    for (int mt = 0; mt < 2; ++mt)
#pragma unroll
        for (int nt = 0; nt < 8; ++nt)
#pragma unroll
            for (int c = 0; c < 4; ++c) acc[mt][nt][c] = 0.0f;

#pragma unroll
    for (int seg = 0; seg < 2; ++seg) {
        const float* A = seg ? A2 : A1;
        const __nv_bfloat16* Wh = seg ? W2h : W1h;
        const __nv_bfloat16* Wl = seg ? W2lo : W1lo;
        for (int k0 = 0; k0 < K; k0 += 32) {
#pragma unroll
            for (int i = 0; i < 4; ++i) {
                int idx = tid + 256 * i;
                int r = idx >> 3, kq = idx & 7;
                float4 v = make_float4(0.f, 0.f, 0.f, 0.f);
                int row = row0 + r;
                if (row < nrows) v = *(const float4*)(A + (size_t)row * K + k0 + 4 * kq);
                __nv_bfloat16 hx = __float2bfloat16(v.x);
                __nv_bfloat16 hy = __float2bfloat16(v.y);
                __nv_bfloat16 hz = __float2bfloat16(v.z);
                __nv_bfloat16 hw = __float2bfloat16(v.w);
                __nv_bfloat16 lx = __float2bfloat16(v.x - __bfloat162float(hx));
                __nv_bfloat16 ly = __float2bfloat16(v.y - __bfloat162float(hy));
                __nv_bfloat16 lz = __float2bfloat16(v.z - __bfloat162float(hz));
                __nv_bfloat16 lw = __float2bfloat16(v.w - __bfloat162float(hw));
                __nv_bfloat162* dh = (__nv_bfloat162*)&sAh[r * LD + 4 * kq];
                __nv_bfloat162* dl = (__nv_bfloat162*)&sAl[r * LD + 4 * kq];
                dh[0] = __halves2bfloat162(hx, hy);
                dh[1] = __halves2bfloat162(hz, hw);
                dl[0] = __halves2bfloat162(lx, ly);
                dl[1] = __halves2bfloat162(lz, lw);
            }
#pragma unroll
            for (int i = 0; i < 8; ++i) {
                int idx = tid + 256 * i;
                int r = idx >> 4, kq = idx & 15;
                size_t gidx = (size_t)(col0 + r) * K + k0 + 2 * kq;
                *(uint32_t*)&sBh[r * LD + 2 * kq] = *(const uint32_t*)(Wh + gidx);
                *(uint32_t*)&sBl[r * LD + 2 * kq] = *(const uint32_t*)(Wl + gidx);
            }
            __syncthreads();

#pragma unroll
            for (int ks = 0; ks < 2; ++ks) {
                int kb = ks * 16;
                uint32_t ah[2][4], al[2][4];
#pragma unroll
                for (int mt = 0; mt < 2; ++mt) {
                    int mr = warp_m * 32 + mt * 16;
                    int o0 = (mr + g) * LD + kb + 2 * t;
                    int o1 = (mr + g + 8) * LD + kb + 2 * t;
                    ah[mt][0] = *(uint32_t*)&sAh[o0];
                    ah[mt][1] = *(uint32_t*)&sAh[o1];
                    ah[mt][2] = *(uint32_t*)&sAh[o0 + 8];
                    ah[mt][3] = *(uint32_t*)&sAh[o1 + 8];
                    al[mt][0] = *(uint32_t*)&sAl[o0];
                    al[mt][1] = *(uint32_t*)&sAl[o1];
                    al[mt][2] = *(uint32_t*)&sAl[o0 + 8];
                    al[mt][3] = *(uint32_t*)&sAl[o1 + 8];
                }
                uint32_t bh[8][2], bl[8][2];
#pragma unroll
                for (int nt = 0; nt < 8; ++nt) {
                    int nr = warp_n * 64 + nt * 8;
                    int o = (nr + g) * LD + kb + 2 * t;
                    bh[nt][0] = *(uint32_t*)&sBh[o];
                    bh[nt][1] = *(uint32_t*)&sBh[o + 8];
                    bl[nt][0] = *(uint32_t*)&sBl[o];
                    bl[nt][1] = *(uint32_t*)&sBl[o + 8];
                }
#pragma unroll
                for (int mt = 0; mt < 2; ++mt)
#pragma unroll
                    for (int nt = 0; nt < 8; ++nt) {
                        MMA_BF16(acc[mt][nt], ah[mt], bh[nt]);
                        MMA_BF16(acc[mt][nt], ah[mt], bl[nt]);
                        MMA_BF16(acc[mt][nt], al[mt], bh[nt]);
                    }
            }
            __syncthreads();
        }
    }

#pragma unroll
    for (int mt = 0; mt < 2; ++mt) {
#pragma unroll
        for (int nt = 0; nt < 8; ++nt) {
            int col = col0 + warp_n * 64 + nt * 8 + 2 * t;
            float b0 = bias[col], b1 = bias[col + 1];
            int r0 = row0 + warp_m * 32 + mt * 16 + g;
            if (r0 < nrows) {
                float v0 = acc[mt][nt][0] + b0;
                float v1 = acc[mt][nt][1] + b1;
                if (RELU) { v0 = fmaxf(v0, 0.f); v1 = fmaxf(v1, 0.f); }
                C[(size_t)r0 * 256 + col] = v0;
                C[(size_t)r0 * 256 + col + 1] = v1;
                if (H16) {
                    C16[(size_t)r0 * 256 + col] = __float2half_rn(v0);
                    C16[(size_t)r0 * 256 + col + 1] = __float2half_rn(v1);
                }
            }
            int r1 = r0 + 8;
            if (r1 < nrows) {
                float v2 = acc[mt][nt][2] + b0;
                float v3 = acc[mt][nt][3] + b1;
                if (RELU) { v2 = fmaxf(v2, 0.f); v3 = fmaxf(v3, 0.f); }
                C[(size_t)r1 * 256 + col] = v2;
                C[(size_t)r1 * 256 + col + 1] = v3;
                if (H16) {
                    C16[(size_t)r1 * 256 + col] = __float2half_rn(v2);
                    C16[(size_t)r1 * 256 + col + 1] = __float2half_rn(v3);
                }
            }
        }
    }
}

// ---------------------------------------------------------------------------
// heads: warp per node, 7 dot products of length 256
__global__ void k_heads(const float* __restrict__ h,
                        const float* __restrict__ Wh1, const float* __restrict__ bh1,
                        const float* __restrict__ Wh2, const float* __restrict__ bh2,
                        float* __restrict__ out1, float* __restrict__ out2) {
    int warp = (blockIdx.x * blockDim.x + threadIdx.x) >> 5;
    int lane = threadIdx.x & 31;
    if (warp >= N_NODES) return;
    const float4* hp = (const float4*)(h + (size_t)warp * HID);
    float4 v0 = hp[lane * 2];
    float4 v1 = hp[lane * 2 + 1];
#pragma unroll
    for (int o = 0; o < 7; ++o) {
        const float* w = (o < 4) ? (Wh1 + (size_t)o * HID) : (Wh2 + (size_t)(o - 4) * HID);
        float4 w0 = ((const float4*)w)[lane * 2];
        float4 w1 = ((const float4*)w)[lane * 2 + 1];
        float p = v0.x * w0.x + v0.y * w0.y + v0.z * w0.z + v0.w * w0.w +
                  v1.x * w1.x + v1.y * w1.y + v1.z * w1.z + v1.w * w1.w;
#pragma unroll
        for (int s = 16; s > 0; s >>= 1) p += __shfl_xor_sync(0xFFFFFFFFu, p, s);
        if (lane == 0) {
            if (o < 4) out1[(size_t)warp * 4 + o] = p + bh1[o];
            else       out2[(size_t)warp * 3 + (o - 4)] = p + bh2[o - 4];
        }
    }
}

// ---------------------------------------------------------------------------
extern "C" void kernel_launch(void* const* d_in, const int* in_sizes, int n_in,
                              void* d_out, int out_size) {
    const float* x   = (const float*)d_in[0];
    const int*   ei  = (const int*)d_in[1];
    const float* W1l = (const float*)d_in[2];
    const float* b1l = (const float*)d_in[3];
    const float* W1r = (const float*)d_in[4];
    const float* W2l = (const float*)d_in[5];
    const float* b2l = (const float*)d_in[6];
    const float* W2r = (const float*)d_in[7];
    const float* Wh1 = (const float*)d_in[8];
    const float* bh1 = (const float*)d_in[9];
    const float* Wh2 = (const float*)d_in[10];
    const float* bh2 = (const float*)d_in[11];

    float* out  = (float*)d_out;
    float* out1 = out;
    float* out2 = out + (size_t)N_NODES * 4;
    float* hout = out + (size_t)N_NODES * 7;

    float *agg, *h1;
    __half *x16, *h116;
    int *deg;
    cudaGetSymbolAddress((void**)&agg, g_agg);
    cudaGetSymbolAddress((void**)&h1, g_h1);
    cudaGetSymbolAddress((void**)&x16, g_x16);
    cudaGetSymbolAddress((void**)&h116, g_h116);
    cudaGetSymbolAddress((void**)&deg, g_deg);

    __nv_bfloat16 *w1lh, *w1ll, *w1rh, *w1rl, *w2lh, *w2ll, *w2rh, *w2rl;
    cudaGetSymbolAddress((void**)&w1lh, g_w1l_h);
    cudaGetSymbolAddress((void**)&w1ll, g_w1l_l);
    cudaGetSymbolAddress((void**)&w1rh, g_w1r_h);
    cudaGetSymbolAddress((void**)&w1rl, g_w1r_l);
    cudaGetSymbolAddress((void**)&w2lh, g_w2l_h);
    cudaGetSymbolAddress((void**)&w2ll, g_w2l_l);
    cudaGetSymbolAddress((void**)&w2rh, g_w2r_h);
    cudaGetSymbolAddress((void**)&w2rl, g_w2r_l);

    const int TB = 256;
    const int edge_blocks = (N_EDGES + TB - 1) / TB;
    const int node_warp_blocks = (N_NODES * 32 + TB - 1) / TB;
    dim3 gemm_grid((N_NODES + 127) / 128, 2);

    // ---- weight split + x fp16 copy ----
    dim3 wgrid((256 * 256 + TB - 1) / TB, 4);
    k_wconv_all<<<wgrid, TB>>>(W1l, W1r, W2l, W2r,
                               w1lh, w1ll, w1rh, w1rl, w2lh, w2ll, w2rh, w2rl);
    {
        int n4 = N_NODES * F_IN / 4;
        k_f2h<<<(n4 + TB - 1) / TB, TB>>>(x, x16, n4);
    }

    // ---- CSR build (shared by both layers) ----
    k_zero_int<<<(N_NODES + TB - 1) / TB, TB>>>(deg, N_NODES);
    k_hist<<<edge_blocks, TB>>>(ei);
    k_scan<<<1, 1024>>>();
    k_fill<<<edge_blocks, TB>>>(ei);

    // ---- layer 1 ----
    k_agg1<<<node_warp_blocks, TB>>>(x16);
    k_gemm_tc<F_IN, true, true><<<gemm_grid, TB>>>(agg, w1lh, w1ll, x, w1rh, w1rl,
                                                   b1l, h1, h116, N_NODES);

    // ---- layer 2 ----
    k_agg2<<<node_warp_blocks, TB>>>(h116);
    k_gemm_tc<HID, false, false><<<gemm_grid, TB>>>(agg, w2lh, w2ll, h1, w2rh, w2rl,
                                                    b2l, hout, (__half*)nullptr, N_NODES);

    // ---- heads ----
    k_heads<<<node_warp_blocks, TB>>>(hout, Wh1, bh1, Wh2, bh2, out1, out2);
}